// round 16
// baseline (speedup 1.0000x reference)
#include <cuda_runtime.h>

#define MAX_EDGES 3200000
#define MAX_NODES 100000
#define EPS 1e-8f

// Scratch (device globals -- no allocation allowed)
__device__ float g_w[MAX_EDGES];
__device__ float g_rowsum[MAX_NODES];

// Pass 1: 4 lanes per edge, direct fp32 gathers (no conversion pass needed).
// Each lane loads one float4 (16B) of the 64B row from each table; the 4
// lanes of a team hit the same 128B line -> 1 wavefront per row touched.
// Two-stage team shfl reduce; lane 0 of team does sigmoid + store + REDG.
__global__ void edge_score_kernel(const int* __restrict__ src,
                                  const int* __restrict__ dst,
                                  const float4* __restrict__ emb1,
                                  const float4* __restrict__ emb2,
                                  int n_edges) {
    int tid = blockIdx.x * blockDim.x + threadIdx.x;
    int e = tid >> 2;
    int q = tid & 3;
    if (e >= n_edges) return;

    unsigned lane = threadIdx.x & 31u;
    unsigned team_mask = 0xFu << (lane & ~3u);  // the 4 cooperating lanes

    int s = src[e];
    int d = dst[e];

    float4 av = __ldg(emb1 + (size_t)s * 4 + q);
    float4 bv = __ldg(emb2 + (size_t)d * 4 + q);

    float acc = fmaf(av.x, bv.x,
                fmaf(av.y, bv.y,
                fmaf(av.z, bv.z, av.w * bv.w)));
    acc += __shfl_xor_sync(team_mask, acc, 1);
    acc += __shfl_xor_sync(team_mask, acc, 2);

    if (q == 0) {
        float w = __frcp_rn(1.0f + __expf(-acc));
        g_w[e] = w;
        atomicAdd(&g_rowsum[s], w);
    }
}

// Pass 2 (R13-proven shape): normalize, 4 edges per thread.
__global__ void normalize_kernel(const int4* __restrict__ src4,
                                 float4* __restrict__ out4,
                                 int n_quads) {
    int i = blockIdx.x * blockDim.x + threadIdx.x;
    if (i >= n_quads) return;
    int4 s = src4[i];
    float4 w = ((const float4*)g_w)[i];
    float4 o;
    o.x = w.x / (g_rowsum[s.x] + EPS);
    o.y = w.y / (g_rowsum[s.y] + EPS);
    o.z = w.z / (g_rowsum[s.z] + EPS);
    o.w = w.w / (g_rowsum[s.w] + EPS);
    out4[i] = o;
}

// Tail (n_edges not divisible by 4)
__global__ void normalize_tail_kernel(const int* __restrict__ src,
                                      float* __restrict__ out,
                                      int start, int n_edges) {
    int e = start + blockIdx.x * blockDim.x + threadIdx.x;
    if (e >= n_edges) return;
    out[e] = g_w[e] / (g_rowsum[src[e]] + EPS);
}

extern "C" void kernel_launch(void* const* d_in, const int* in_sizes, int n_in,
                              void* d_out, int out_size) {
    const int*    src  = (const int*)d_in[0];
    const int*    dst  = (const int*)d_in[1];
    const float4* emb1 = (const float4*)d_in[2];
    const float4* emb2 = (const float4*)d_in[3];
    float*        out  = (float*)d_out;

    int n_edges = in_sizes[0];
    int n_nodes = in_sizes[2] / 16;

    const int T = 256;

    // Zero rowsum via an async memset node (graph-capturable, no kernel ramp)
    void* rowsum_ptr = nullptr;
    cudaGetSymbolAddress(&rowsum_ptr, g_rowsum);
    cudaMemsetAsync(rowsum_ptr, 0, (size_t)n_nodes * sizeof(float));

    long long score_threads = 4LL * n_edges;
    edge_score_kernel<<<(int)((score_threads + T - 1) / T), T>>>(
        src, dst, emb1, emb2, n_edges);

    int n_quads = n_edges / 4;
    if (n_quads > 0)
        normalize_kernel<<<(n_quads + T - 1) / T, T>>>((const int4*)src,
                                                       (float4*)out, n_quads);
    int tail_start = n_quads * 4;
    int tail = n_edges - tail_start;
    if (tail > 0)
        normalize_tail_kernel<<<1, 64>>>(src, out, tail_start, n_edges);
}